// round 5
// baseline (speedup 1.0000x reference)
#include <cuda_runtime.h>

// Problem dims (fixed per reference)
#define NN   20000
#define EE   40000
#define FAx  75
#define FBx  12
#define CCx  100
#define GGx  1000
#define EPSV 1e-5f

#define TBE 32   // edges per block in the edge kernel (8 per warp)

// Scratch (static device arrays: no allocation allowed)
__device__ float g_h[NN * CCx];     // node features h [N, C]
__device__ float g_stats[2 * CCx];  // [sum, sumsq] per channel

// ---------------------------------------------------------------------------
// packed f32x2 FMA (FFMA2) — only reachable via PTX
// ---------------------------------------------------------------------------
union F2U { float2 f2; unsigned long long u; };

__device__ __forceinline__ float2 ffma2(float2 a, float2 b, float2 c) {
    F2U ua, ub, uc, ud;
    ua.f2 = a; ub.f2 = b; uc.f2 = c;
    asm("fma.rn.f32x2 %0, %1, %2, %3;"
        : "=l"(ud.u) : "l"(ua.u), "l"(ub.u), "l"(uc.u));
    return ud.f2;
}

__device__ __forceinline__ float2 relu2(float2 v) {
    return make_float2(fmaxf(v.x, 0.f), fmaxf(v.y, 0.f));
}

// ---------------------------------------------------------------------------
// K0: zero the batch-stat accumulator
// ---------------------------------------------------------------------------
__global__ void k_zero() {
    int t = threadIdx.x;
    if (t < 2 * CCx) g_stats[t] = 0.f;
}

// ---------------------------------------------------------------------------
// K1: h[n,c] = x[n,:] @ W_root[:,c] + bias[c]  (one block/node, packed pairs)
// ---------------------------------------------------------------------------
__global__ void k_root(const float* __restrict__ x,
                       const float* __restrict__ Wr,
                       const float* __restrict__ bias) {
    __shared__ float xs[FAx];
    int n = blockIdx.x;
    int tid = threadIdx.x;              // blockDim = 64
    for (int i = tid; i < FAx; i += 64) xs[i] = x[n * FAx + i];
    __syncthreads();
    if (tid < CCx / 2) {
        int c = 2 * tid;
        float2 acc = *(const float2*)&bias[c];
#pragma unroll
        for (int i = 0; i < FAx; i++) {
            float2 w = *(const float2*)&Wr[i * CCx + c];
            float xv = xs[i];
            acc = ffma2(make_float2(xv, xv), w, acc);
        }
        *(float2*)&g_h[n * CCx + c] = acc;
    }
}

// ---------------------------------------------------------------------------
// K2: fused NNConv edge kernel (f32x2 packed).
//   t[i,c] = b1[i*C+c] + sum_j ea[e,j]*W1[j, i*C+c]
//   msg[e,c] = sum_i x_src[e,i] * relu(t[i,c]);  atomicAdd into g_h[dst[e],:]
// Layout: 128 thr = 4 warps; warp w owns edges [8w, 8w+8); lane owns channel
// pairs p0=lane, p1=32+lane (clamped to 49, masked at atomic).
// ea / x staged in smem pre-DUPLICATED (v,v) so packed operands come from
// single LDS.128 broadcasts.
// ---------------------------------------------------------------------------
__global__ void __launch_bounds__(128, 4)
k_edge(const float* __restrict__ x,
       const float* __restrict__ ea,
       const float* __restrict__ W1,
       const float* __restrict__ b1,
       const int*   __restrict__ eidx) {
    __shared__ float ea_d[FBx][2 * TBE];   // duplicated pairs
    __shared__ float xs_d[FAx][2 * TBE];   // duplicated pairs
    __shared__ int   dst_s[TBE];

    const int tid = threadIdx.x;
    const int e0  = blockIdx.x * TBE;

    for (int idx = tid; idx < TBE * FBx; idx += 128) {
        int e = idx / FBx, j = idx - e * FBx;
        float v = ea[(e0 + e) * FBx + j];
        ea_d[j][2 * e] = v; ea_d[j][2 * e + 1] = v;
    }
    if (tid < TBE) dst_s[tid] = eidx[EE + e0 + tid];
    for (int idx = tid; idx < TBE * FAx; idx += 128) {
        int e = idx / FAx, i = idx - e * FAx;
        int s = eidx[e0 + e];
        float v = x[s * FAx + i];
        xs_d[i][2 * e] = v; xs_d[i][2 * e + 1] = v;
    }
    __syncthreads();

    const int lane = tid & 31;
    const int w    = tid >> 5;
    const int p1   = 32 + lane;
    const bool ok1 = (p1 < CCx / 2);
    const int p1c  = ok1 ? p1 : (CCx / 2 - 1);
    const int c0   = 2 * lane;     // channels c0, c0+1
    const int c1   = 2 * p1c;      // channels c1, c1+1
    const int ebase = 16 * w;      // duplicated-index base for this warp

    float2 acc[8][2];
#pragma unroll
    for (int e = 0; e < 8; e++) {
        acc[e][0] = make_float2(0.f, 0.f);
        acc[e][1] = make_float2(0.f, 0.f);
    }

    for (int i = 0; i < FAx; i++) {
        const int col = i * CCx;
        const float2 bv0 = *(const float2*)&b1[col + c0];
        const float2 bv1 = *(const float2*)&b1[col + c1];

        float2 t[8][2];
        // j = 0 folds the bias init
        {
            const float* Wj = W1 + 0 * (FAx * CCx) + col;
            float2 wv0 = *(const float2*)&Wj[c0];
            float2 wv1 = *(const float2*)&Wj[c1];
#pragma unroll
            for (int q = 0; q < 4; q++) {
                float4 A = *(const float4*)&ea_d[0][ebase + 4 * q];
                float2 a0 = make_float2(A.x, A.y);
                float2 a1 = make_float2(A.z, A.w);
                t[2*q  ][0] = ffma2(a0, wv0, bv0);
                t[2*q  ][1] = ffma2(a0, wv1, bv1);
                t[2*q+1][0] = ffma2(a1, wv0, bv0);
                t[2*q+1][1] = ffma2(a1, wv1, bv1);
            }
        }
#pragma unroll
        for (int j = 1; j < FBx; j++) {
            const float* Wj = W1 + j * (FAx * CCx) + col;
            float2 wv0 = *(const float2*)&Wj[c0];
            float2 wv1 = *(const float2*)&Wj[c1];
#pragma unroll
            for (int q = 0; q < 4; q++) {
                float4 A = *(const float4*)&ea_d[j][ebase + 4 * q];
                float2 a0 = make_float2(A.x, A.y);
                float2 a1 = make_float2(A.z, A.w);
                t[2*q  ][0] = ffma2(a0, wv0, t[2*q  ][0]);
                t[2*q  ][1] = ffma2(a0, wv1, t[2*q  ][1]);
                t[2*q+1][0] = ffma2(a1, wv0, t[2*q+1][0]);
                t[2*q+1][1] = ffma2(a1, wv1, t[2*q+1][1]);
            }
        }
        // msg accumulation: acc += x_src[i] * relu(t)
#pragma unroll
        for (int q = 0; q < 4; q++) {
            float4 X = *(const float4*)&xs_d[i][ebase + 4 * q];
            float2 x0 = make_float2(X.x, X.y);
            float2 x1 = make_float2(X.z, X.w);
            acc[2*q  ][0] = ffma2(x0, relu2(t[2*q  ][0]), acc[2*q  ][0]);
            acc[2*q  ][1] = ffma2(x0, relu2(t[2*q  ][1]), acc[2*q  ][1]);
            acc[2*q+1][0] = ffma2(x1, relu2(t[2*q+1][0]), acc[2*q+1][0]);
            acc[2*q+1][1] = ffma2(x1, relu2(t[2*q+1][1]), acc[2*q+1][1]);
        }
    }

    // scatter-add messages into destination nodes
#pragma unroll
    for (int e = 0; e < 8; e++) {
        int d = dst_s[8 * w + e];
        float* hr = &g_h[d * CCx];
        atomicAdd(hr + c0,     acc[e][0].x);
        atomicAdd(hr + c0 + 1, acc[e][0].y);
        if (ok1) {
            atomicAdd(hr + c1,     acc[e][1].x);
            atomicAdd(hr + c1 + 1, acc[e][1].y);
        }
    }
}

// ---------------------------------------------------------------------------
// K3: relu in place + per-channel sum/sumsq, register-accumulated.
// Thread owns fixed channel c=tid; rows grid-strided -> coalesced rows.
// ---------------------------------------------------------------------------
__global__ void k_stats() {
    int c = threadIdx.x;               // blockDim = 128, active if c < C
    if (c < CCx) {
        float s = 0.f, q = 0.f;
        for (int n = blockIdx.x; n < NN; n += gridDim.x) {
            float r = fmaxf(g_h[n * CCx + c], 0.f);
            g_h[n * CCx + c] = r;
            s += r; q += r * r;
        }
        atomicAdd(&g_stats[c], s);
        atomicAdd(&g_stats[CCx + c], q);
    }
}

// ---------------------------------------------------------------------------
// K4: fused BN-apply + global_add_pool + output head, one block per molecule.
// Uses  sum_n norm(h) = gamma*rstd*(S - cnt*mean) + cnt*beta  so raw h is
// pooled first (no per-element normalize, no global atomics).
// ---------------------------------------------------------------------------
__device__ __forceinline__ int lower_bound_batch(const int* __restrict__ b, int key) {
    int lo = 0, hi = NN;
    while (lo < hi) {
        int mid = (lo + hi) >> 1;
        if (b[mid] < key) lo = mid + 1; else hi = mid;
    }
    return lo;
}

__global__ void k_pool_out(const float* __restrict__ gamma,
                           const float* __restrict__ beta,
                           const float* __restrict__ Wout,
                           const float* __restrict__ bout,
                           const int*   __restrict__ batch,
                           float* __restrict__ out) {
    __shared__ int s_lo, s_hi;
    __shared__ float red[128];
    const int g = blockIdx.x;
    const int tid = threadIdx.x;       // blockDim = 128
    if (tid == 0) s_lo = lower_bound_batch(batch, g);
    if (tid == 1) s_hi = lower_bound_batch(batch, g + 1);
    __syncthreads();
    const int lo = s_lo, hi = s_hi;

    float val = 0.f;
    if (tid < CCx) {
        float S = 0.f;
        for (int n = lo; n < hi; n++) S += g_h[n * CCx + tid];
        float cnt  = (float)(hi - lo);
        float mean = g_stats[tid] * (1.f / NN);
        float var  = g_stats[CCx + tid] * (1.f / NN) - mean * mean;
        float rstd = rsqrtf(var + EPSV);
        float pooled = gamma[tid] * rstd * (S - cnt * mean) + cnt * beta[tid];
        val = fmaxf(pooled, 0.f) * Wout[tid];
    }
    red[tid] = val;
    __syncthreads();
#pragma unroll
    for (int o = 64; o; o >>= 1) {
        if (tid < o) red[tid] += red[tid + o];
        __syncthreads();
    }
    if (tid == 0) out[g] = red[0] + bout[0];
}

// ---------------------------------------------------------------------------
extern "C" void kernel_launch(void* const* d_in, const int* in_sizes, int n_in,
                              void* d_out, int out_size) {
    const float* x     = (const float*)d_in[0];   // [N, FA]
    const float* ea    = (const float*)d_in[1];   // [E, FB]
    const float* W1    = (const float*)d_in[2];   // [FB, FA*C]
    const float* b1    = (const float*)d_in[3];   // [FA*C]
    const float* Wr    = (const float*)d_in[4];   // [FA, C]
    const float* bias  = (const float*)d_in[5];   // [C]
    const float* gamma = (const float*)d_in[6];   // [C]
    const float* beta  = (const float*)d_in[7];   // [C]
    const float* Wout  = (const float*)d_in[8];   // [C, 1]
    const float* bout  = (const float*)d_in[9];   // [1]
    const int*   eidx  = (const int*)d_in[10];    // [2, E]
    const int*   batch = (const int*)d_in[11];    // [N]
    float* out = (float*)d_out;                   // [G, 1]

    k_zero<<<1, 256>>>();
    k_root<<<NN, 64>>>(x, Wr, bias);
    k_edge<<<EE / TBE, 128>>>(x, ea, W1, b1, eidx);
    k_stats<<<256, 128>>>();
    k_pool_out<<<GGx, 128>>>(gamma, beta, Wout, bout, batch, out);
}

// round 9
// speedup vs baseline: 1.9417x; 1.9417x over previous
#include <cuda_runtime.h>

// Problem dims (fixed per reference)
#define NN   20000
#define EE   40000
#define FAx  75
#define FBx  12
#define CCx  100
#define GGx  1000
#define EPSV 1e-5f

#define TBE 16   // edges per block (4 per warp)

// Scratch (static device arrays: no allocation allowed)
__device__ float g_h[NN * CCx];     // node features h [N, C] (pre-relu)
__device__ float g_stats[2 * CCx];  // [sum, sumsq] per channel of relu(h)

// ---------------------------------------------------------------------------
// packed f32x2 FMA (FFMA2) — only reachable via PTX
// ---------------------------------------------------------------------------
union F2U { float2 f2; unsigned long long u; };

__device__ __forceinline__ float2 ffma2(float2 a, float2 b, float2 c) {
    F2U ua, ub, uc, ud;
    ua.f2 = a; ub.f2 = b; uc.f2 = c;
    asm("fma.rn.f32x2 %0, %1, %2, %3;"
        : "=l"(ud.u) : "l"(ua.u), "l"(ub.u), "l"(uc.u));
    return ud.f2;
}
__device__ __forceinline__ float2 relu2(float2 v) {
    return make_float2(fmaxf(v.x, 0.f), fmaxf(v.y, 0.f));
}

// ---------------------------------------------------------------------------
// K0: zero the batch-stat accumulator
// ---------------------------------------------------------------------------
__global__ void k_zero() {
    int t = threadIdx.x;
    if (t < 2 * CCx) g_stats[t] = 0.f;
}

// ---------------------------------------------------------------------------
// K1: h[n,c] = x[n,:] @ W_root[:,c] + bias[c]
// 256 threads = 8 warps = 8 nodes per block; lane<25 owns channel quad 4*lane.
// ---------------------------------------------------------------------------
__global__ void __launch_bounds__(256)
k_root(const float* __restrict__ x,
       const float* __restrict__ Wr,
       const float* __restrict__ bias) {
    __shared__ float xs[8][FAx + 1];
    const int tid = threadIdx.x;
    const int n0  = blockIdx.x * 8;

    for (int idx = tid; idx < 8 * FAx; idx += 256) {
        int e = idx / FAx, i = idx - e * FAx;
        int n = n0 + e;
        xs[e][i] = (n < NN) ? x[n * FAx + i] : 0.f;
    }
    __syncthreads();

    const int w = tid >> 5, lane = tid & 31;
    const int n = n0 + w;
    if (n >= NN || lane >= CCx / 4) return;
    const int c = 4 * lane;

    float4 B = *(const float4*)&bias[c];
    float2 a0 = make_float2(B.x, B.y);
    float2 a1 = make_float2(B.z, B.w);
#pragma unroll
    for (int i = 0; i < FAx; i++) {
        float xv = xs[w][i];
        float2 xp = make_float2(xv, xv);
        float4 Wv = *(const float4*)&Wr[i * CCx + c];
        a0 = ffma2(xp, make_float2(Wv.x, Wv.y), a0);
        a1 = ffma2(xp, make_float2(Wv.z, Wv.w), a1);
    }
    float4 o; o.x = a0.x; o.y = a0.y; o.z = a1.x; o.w = a1.y;
    *(float4*)&g_h[n * CCx + c] = o;
}

// ---------------------------------------------------------------------------
// K2: fused NNConv edge kernel (f32x2, small tile).
//   t[i,c] = b1[i*C+c] + sum_j ea[e,j]*W1[j, i*C+c]
//   msg[e,c] = sum_i x_src[e,i] * relu(t[i,c]); atomicAdd into g_h[dst[e],:]
// 128 thr = 4 warps; warp w owns edges [4w,4w+4); lane<25 owns channels
// 4*lane..4*lane+3 (two f32 pairs). ea / x staged duplicated (v,v) so packed
// operands come from single broadcast LDS.128.
// ---------------------------------------------------------------------------
__global__ void __launch_bounds__(128, 6)
k_edge(const float* __restrict__ x,
       const float* __restrict__ ea,
       const float* __restrict__ W1,
       const float* __restrict__ b1,
       const int*   __restrict__ eidx) {
    __shared__ float ea_d[FBx][2 * TBE];   // duplicated pairs [12][32]
    __shared__ float xs_d[FAx][2 * TBE];   // duplicated pairs [75][32]
    __shared__ int   dst_s[TBE];

    const int tid = threadIdx.x;
    const int e0  = blockIdx.x * TBE;

    for (int idx = tid; idx < TBE * FBx; idx += 128) {
        int e = idx / FBx, j = idx - e * FBx;
        float v = ea[(e0 + e) * FBx + j];
        ea_d[j][2 * e] = v; ea_d[j][2 * e + 1] = v;
    }
    if (tid < TBE) dst_s[tid] = eidx[EE + e0 + tid];
    for (int idx = tid; idx < TBE * FAx; idx += 128) {
        int e = idx / FAx, i = idx - e * FAx;
        int s = eidx[e0 + e];
        float v = x[s * FAx + i];
        xs_d[i][2 * e] = v; xs_d[i][2 * e + 1] = v;
    }
    __syncthreads();

    const int lane  = tid & 31;
    const int w     = tid >> 5;
    const bool ok   = (lane < CCx / 4);        // 25 active lanes
    const int  lc   = ok ? lane : (CCx / 4 - 1);
    const int  c    = 4 * lc;                  // channels c..c+3
    const int  eb   = 8 * w;                   // duplicated idx base (4 edges)

    float2 acc[4][2];
#pragma unroll
    for (int e = 0; e < 4; e++) {
        acc[e][0] = make_float2(0.f, 0.f);
        acc[e][1] = make_float2(0.f, 0.f);
    }

    for (int i = 0; i < FAx; i++) {
        const int col = i * CCx + c;
        float4 B = *(const float4*)&b1[col];
        const float2 bv0 = make_float2(B.x, B.y);
        const float2 bv1 = make_float2(B.z, B.w);

        float2 t[4][2];
        // j = 0 folds bias init
        {
            float4 Wv = *(const float4*)&W1[col];           // j=0 row
            float2 wv0 = make_float2(Wv.x, Wv.y);
            float2 wv1 = make_float2(Wv.z, Wv.w);
            float4 A0 = *(const float4*)&ea_d[0][eb];       // (e0,e0,e1,e1)
            float4 A1 = *(const float4*)&ea_d[0][eb + 4];   // (e2,e2,e3,e3)
            float2 a00 = make_float2(A0.x, A0.y), a01 = make_float2(A0.z, A0.w);
            float2 a10 = make_float2(A1.x, A1.y), a11 = make_float2(A1.z, A1.w);
            t[0][0] = ffma2(a00, wv0, bv0);  t[0][1] = ffma2(a00, wv1, bv1);
            t[1][0] = ffma2(a01, wv0, bv0);  t[1][1] = ffma2(a01, wv1, bv1);
            t[2][0] = ffma2(a10, wv0, bv0);  t[2][1] = ffma2(a10, wv1, bv1);
            t[3][0] = ffma2(a11, wv0, bv0);  t[3][1] = ffma2(a11, wv1, bv1);
        }
#pragma unroll
        for (int j = 1; j < FBx; j++) {
            float4 Wv = *(const float4*)&W1[j * (FAx * CCx) + col];
            float2 wv0 = make_float2(Wv.x, Wv.y);
            float2 wv1 = make_float2(Wv.z, Wv.w);
            float4 A0 = *(const float4*)&ea_d[j][eb];
            float4 A1 = *(const float4*)&ea_d[j][eb + 4];
            float2 a00 = make_float2(A0.x, A0.y), a01 = make_float2(A0.z, A0.w);
            float2 a10 = make_float2(A1.x, A1.y), a11 = make_float2(A1.z, A1.w);
            t[0][0] = ffma2(a00, wv0, t[0][0]);  t[0][1] = ffma2(a00, wv1, t[0][1]);
            t[1][0] = ffma2(a01, wv0, t[1][0]);  t[1][1] = ffma2(a01, wv1, t[1][1]);
            t[2][0] = ffma2(a10, wv0, t[2][0]);  t[2][1] = ffma2(a10, wv1, t[2][1]);
            t[3][0] = ffma2(a11, wv0, t[3][0]);  t[3][1] = ffma2(a11, wv1, t[3][1]);
        }
        // acc += x_src[i] * relu(t)
        float4 X0 = *(const float4*)&xs_d[i][eb];
        float4 X1 = *(const float4*)&xs_d[i][eb + 4];
        float2 x00 = make_float2(X0.x, X0.y), x01 = make_float2(X0.z, X0.w);
        float2 x10 = make_float2(X1.x, X1.y), x11 = make_float2(X1.z, X1.w);
        acc[0][0] = ffma2(x00, relu2(t[0][0]), acc[0][0]);
        acc[0][1] = ffma2(x00, relu2(t[0][1]), acc[0][1]);
        acc[1][0] = ffma2(x01, relu2(t[1][0]), acc[1][0]);
        acc[1][1] = ffma2(x01, relu2(t[1][1]), acc[1][1]);
        acc[2][0] = ffma2(x10, relu2(t[2][0]), acc[2][0]);
        acc[2][1] = ffma2(x10, relu2(t[2][1]), acc[2][1]);
        acc[3][0] = ffma2(x11, relu2(t[3][0]), acc[3][0]);
        acc[3][1] = ffma2(x11, relu2(t[3][1]), acc[3][1]);
    }

    // scatter-add messages into destination nodes
    if (ok) {
#pragma unroll
        for (int e = 0; e < 4; e++) {
            int d = dst_s[4 * w + e];
            float* hr = &g_h[d * CCx + c];
            atomicAdd(hr + 0, acc[e][0].x);
            atomicAdd(hr + 1, acc[e][0].y);
            atomicAdd(hr + 2, acc[e][1].x);
            atomicAdd(hr + 3, acc[e][1].y);
        }
    }
}

// ---------------------------------------------------------------------------
// K3: per-channel sum & sumsq of relu(h). Read-only, float2, 4-way unrolled.
// Thread owns channel pair 2*tid; rows strided by grid.
// ---------------------------------------------------------------------------
__global__ void __launch_bounds__(64)
k_stats() {
    const int c2 = threadIdx.x;            // blockDim = 64, active < 50
    if (c2 >= CCx / 2) return;
    const int cb = 2 * c2;
    float2 s = make_float2(0.f, 0.f);
    float2 q = make_float2(0.f, 0.f);
    const int stride = gridDim.x;
    int n = blockIdx.x;
    for (; n + 3 * stride < NN; n += 4 * stride) {
        float2 a = *(const float2*)&g_h[(n              ) * CCx + cb];
        float2 b = *(const float2*)&g_h[(n +     stride) * CCx + cb];
        float2 cc = *(const float2*)&g_h[(n + 2 * stride) * CCx + cb];
        float2 d = *(const float2*)&g_h[(n + 3 * stride) * CCx + cb];
        a = relu2(a); b = relu2(b); cc = relu2(cc); d = relu2(d);
        s.x += a.x + b.x + cc.x + d.x;  s.y += a.y + b.y + cc.y + d.y;
        q.x += a.x*a.x + b.x*b.x + cc.x*cc.x + d.x*d.x;
        q.y += a.y*a.y + b.y*b.y + cc.y*cc.y + d.y*d.y;
    }
    for (; n < NN; n += stride) {
        float2 a = relu2(*(const float2*)&g_h[n * CCx + cb]);
        s.x += a.x; s.y += a.y;
        q.x += a.x*a.x; q.y += a.y*a.y;
    }
    atomicAdd(&g_stats[cb],           s.x);
    atomicAdd(&g_stats[cb + 1],       s.y);
    atomicAdd(&g_stats[CCx + cb],     q.x);
    atomicAdd(&g_stats[CCx + cb + 1], q.y);
}

// ---------------------------------------------------------------------------
// K4: fused BN-apply + global_add_pool + output head, one block per molecule.
//   sum_n norm(relu(h)) = gamma*rstd*(S - cnt*mean) + cnt*beta
// ---------------------------------------------------------------------------
__device__ __forceinline__ int lower_bound_batch(const int* __restrict__ b, int key) {
    int lo = 0, hi = NN;
    while (lo < hi) {
        int mid = (lo + hi) >> 1;
        if (b[mid] < key) lo = mid + 1; else hi = mid;
    }
    return lo;
}

__global__ void __launch_bounds__(128)
k_pool_out(const float* __restrict__ gamma,
           const float* __restrict__ beta,
           const float* __restrict__ Wout,
           const float* __restrict__ bout,
           const int*   __restrict__ batch,
           float* __restrict__ out) {
    __shared__ int s_lo, s_hi;
    __shared__ float red[128];
    const int g = blockIdx.x;
    const int tid = threadIdx.x;
    if (tid == 0) s_lo = lower_bound_batch(batch, g);
    if (tid == 1) s_hi = lower_bound_batch(batch, g + 1);
    __syncthreads();
    const int lo = s_lo, hi = s_hi;

    float val = 0.f;
    if (tid < CCx) {
        float S = 0.f;
        for (int n = lo; n < hi; n++)
            S += fmaxf(g_h[n * CCx + tid], 0.f);
        float cnt  = (float)(hi - lo);
        float mean = g_stats[tid] * (1.f / NN);
        float var  = g_stats[CCx + tid] * (1.f / NN) - mean * mean;
        float rstd = rsqrtf(var + EPSV);
        float pooled = gamma[tid] * rstd * (S - cnt * mean) + cnt * beta[tid];
        val = fmaxf(pooled, 0.f) * Wout[tid];
    }
    red[tid] = val;
    __syncthreads();
#pragma unroll
    for (int o = 64; o; o >>= 1) {
        if (tid < o) red[tid] += red[tid + o];
        __syncthreads();
    }
    if (tid == 0) out[g] = red[0] + bout[0];
}

// ---------------------------------------------------------------------------
extern "C" void kernel_launch(void* const* d_in, const int* in_sizes, int n_in,
                              void* d_out, int out_size) {
    const float* x     = (const float*)d_in[0];   // [N, FA]
    const float* ea    = (const float*)d_in[1];   // [E, FB]
    const float* W1    = (const float*)d_in[2];   // [FB, FA*C]
    const float* b1    = (const float*)d_in[3];   // [FA*C]
    const float* Wr    = (const float*)d_in[4];   // [FA, C]
    const float* bias  = (const float*)d_in[5];   // [C]
    const float* gamma = (const float*)d_in[6];   // [C]
    const float* beta  = (const float*)d_in[7];   // [C]
    const float* Wout  = (const float*)d_in[8];   // [C, 1]
    const float* bout  = (const float*)d_in[9];   // [1]
    const int*   eidx  = (const int*)d_in[10];    // [2, E]
    const int*   batch = (const int*)d_in[11];    // [N]
    float* out = (float*)d_out;                   // [G, 1]

    k_zero<<<1, 256>>>();
    k_root<<<(NN + 7) / 8, 256>>>(x, Wr, bias);
    k_edge<<<EE / TBE, 128>>>(x, ea, W1, b1, eidx);
    k_stats<<<1000, 64>>>();
    k_pool_out<<<GGx, 128>>>(gamma, beta, Wout, bout, batch, out);
}

// round 14
// speedup vs baseline: 3.2402x; 1.6688x over previous
#include <cuda_runtime.h>
#include <cstdint>

// Problem dims (fixed per reference)
#define NN   20000
#define EE   40000
#define FAx  75
#define FBx  12
#define CCx  100
#define GGx  1000
#define EPSV 1e-5f

#define TBE 16   // edges per block (4 per warp)

// Scratch (static device arrays: no allocation allowed)
__device__ float g_h[NN * CCx];     // node features h [N, C] (pre-relu)
__device__ float g_stats[2 * CCx];  // [sum, sumsq] per channel of relu(h)

// ---------------------------------------------------------------------------
// packed f32x2 FMA (FFMA2) — only reachable via PTX
// ---------------------------------------------------------------------------
union F2U { float2 f2; unsigned long long u; };

__device__ __forceinline__ float2 ffma2(float2 a, float2 b, float2 c) {
    F2U ua, ub, uc, ud;
    ua.f2 = a; ub.f2 = b; uc.f2 = c;
    asm("fma.rn.f32x2 %0, %1, %2, %3;"
        : "=l"(ud.u) : "l"(ua.u), "l"(ub.u), "l"(uc.u));
    return ud.f2;
}
__device__ __forceinline__ float2 relu2(float2 v) {
    return make_float2(fmaxf(v.x, 0.f), fmaxf(v.y, 0.f));
}

// cp.async 16B helpers
__device__ __forceinline__ void cp_async16(void* sptr, const void* gptr) {
    unsigned int sa = (unsigned int)__cvta_generic_to_shared(sptr);
    asm volatile("cp.async.ca.shared.global [%0], [%1], 16;" :: "r"(sa), "l"(gptr));
}
#define CP_COMMIT()  asm volatile("cp.async.commit_group;")
#define CP_WAIT(n)   asm volatile("cp.async.wait_group %0;" :: "n"(n))

// ---------------------------------------------------------------------------
// K0: zero the batch-stat accumulator
// ---------------------------------------------------------------------------
__global__ void k_zero() {
    int t = threadIdx.x;
    if (t < 2 * CCx) g_stats[t] = 0.f;
}

// ---------------------------------------------------------------------------
// K1: h[n,c] = x[n,:] @ W_root[:,c] + bias[c]
// 256 threads = 8 warps = 8 nodes per block; lane<25 owns channel quad 4*lane.
// ---------------------------------------------------------------------------
__global__ void __launch_bounds__(256)
k_root(const float* __restrict__ x,
       const float* __restrict__ Wr,
       const float* __restrict__ bias) {
    __shared__ float xs[8][FAx + 1];
    const int tid = threadIdx.x;
    const int n0  = blockIdx.x * 8;

    for (int idx = tid; idx < 8 * FAx; idx += 256) {
        int e = idx / FAx, i = idx - e * FAx;
        int n = n0 + e;
        xs[e][i] = (n < NN) ? x[n * FAx + i] : 0.f;
    }
    __syncthreads();

    const int w = tid >> 5, lane = tid & 31;
    const int n = n0 + w;
    if (n >= NN || lane >= CCx / 4) return;
    const int c = 4 * lane;

    float4 B = *(const float4*)&bias[c];
    float2 a0 = make_float2(B.x, B.y);
    float2 a1 = make_float2(B.z, B.w);
#pragma unroll
    for (int i = 0; i < FAx; i++) {
        float xv = xs[w][i];
        float2 xp = make_float2(xv, xv);
        float4 Wv = *(const float4*)&Wr[i * CCx + c];
        a0 = ffma2(xp, make_float2(Wv.x, Wv.y), a0);
        a1 = ffma2(xp, make_float2(Wv.z, Wv.w), a1);
    }
    float4 o; o.x = a0.x; o.y = a0.y; o.z = a1.x; o.w = a1.y;
    *(float4*)&g_h[n * CCx + c] = o;
}

// ---------------------------------------------------------------------------
// K2: fused NNConv edge kernel, cp.async double-buffered W1 staging.
//   t[i,c] = b1[i*C+c] + sum_j ea[e,j]*W1[j, i*C+c]
//   msg[e,c] = sum_i x_src[e,i] * relu(t[i,c]); atomicAdd into g_h[dst[e],:]
// 128 thr = 4 warps; warp w owns edges [4w,4w+4); lane<25 owns channels
// 4*lane..4*lane+3 (two f32 pairs). ea / x staged duplicated (v,v).
// Per i, the 12x100 W1 slice + 100-wide b1 slice live in smem (2 buffers),
// prefetched one i ahead -> inner loop is pure LDS + FFMA2.
// ---------------------------------------------------------------------------
__global__ void __launch_bounds__(128, 5)
k_edge(const float* __restrict__ x,
       const float* __restrict__ ea,
       const float* __restrict__ W1,
       const float* __restrict__ b1,
       const int*   __restrict__ eidx) {
    __shared__ float W_s[2][FBx][CCx];     // 9.6 KB
    __shared__ float b_s[2][CCx];          // 0.8 KB
    __shared__ float ea_d[FBx][2 * TBE];   // duplicated pairs [12][32]
    __shared__ float xs_d[FAx][2 * TBE];   // duplicated pairs [75][32]
    __shared__ int   dst_s[TBE];

    const int tid = threadIdx.x;
    const int e0  = blockIdx.x * TBE;

    // ---- stage edge data ----
    for (int idx = tid; idx < TBE * FBx; idx += 128) {
        int e = idx / FBx, j = idx - e * FBx;
        float v = ea[(e0 + e) * FBx + j];
        ea_d[j][2 * e] = v; ea_d[j][2 * e + 1] = v;
    }
    if (tid < TBE) dst_s[tid] = eidx[EE + e0 + tid];
    for (int idx = tid; idx < TBE * FAx; idx += 128) {
        int e = idx / FAx, i = idx - e * FAx;
        int s = eidx[e0 + e];
        float v = x[s * FAx + i];
        xs_d[i][2 * e] = v; xs_d[i][2 * e + 1] = v;
    }

    // ---- prefetch W1/b1 slice for i = 0 ----
    // 300 float4 of W slice + 25 float4 of b1 slice = 325 cp.async per slice
    {
        const float* Wsrc = W1;          // + i*100, i=0
        const float* bsrc = b1;
        for (int idx = tid; idx < 325; idx += 128) {
            if (idx < 300) {
                int j = idx / 25, q = idx - 25 * j;
                cp_async16(&W_s[0][j][4 * q], Wsrc + j * (FAx * CCx) + 4 * q);
            } else {
                int q = idx - 300;
                cp_async16(&b_s[0][4 * q], bsrc + 4 * q);
            }
        }
        CP_COMMIT();
    }

    const int lane  = tid & 31;
    const int w     = tid >> 5;
    const bool ok   = (lane < CCx / 4);        // 25 active lanes
    const int  lc   = ok ? lane : (CCx / 4 - 1);
    const int  c    = 4 * lc;                  // channels c..c+3
    const int  eb   = 8 * w;                   // duplicated idx base (4 edges)

    float2 acc[4][2];
#pragma unroll
    for (int e = 0; e < 4; e++) {
        acc[e][0] = make_float2(0.f, 0.f);
        acc[e][1] = make_float2(0.f, 0.f);
    }

    for (int i = 0; i < FAx; i++) {
        const int buf = i & 1;
        // prefetch next slice into the other buffer
        if (i + 1 < FAx) {
            const float* Wsrc = W1 + (i + 1) * CCx;
            const float* bsrc = b1 + (i + 1) * CCx;
            float* Wdst = &W_s[buf ^ 1][0][0];
            float* bdst = &b_s[buf ^ 1][0];
            for (int idx = tid; idx < 325; idx += 128) {
                if (idx < 300) {
                    int j = idx / 25, q = idx - 25 * j;
                    cp_async16(Wdst + j * CCx + 4 * q, Wsrc + j * (FAx * CCx) + 4 * q);
                } else {
                    int q = idx - 300;
                    cp_async16(bdst + 4 * q, bsrc + 4 * q);
                }
            }
            CP_COMMIT();
            CP_WAIT(1);          // slice i complete (group before the one just committed)
        } else {
            CP_WAIT(0);
        }
        __syncthreads();         // slice i visible to all warps (also covers ea/xs on i=0)

        float4 B = *(const float4*)&b_s[buf][c];
        const float2 bv0 = make_float2(B.x, B.y);
        const float2 bv1 = make_float2(B.z, B.w);

        float2 t[4][2];
        // j = 0 folds bias init
        {
            float4 Wv = *(const float4*)&W_s[buf][0][c];
            float2 wv0 = make_float2(Wv.x, Wv.y);
            float2 wv1 = make_float2(Wv.z, Wv.w);
            float4 A0 = *(const float4*)&ea_d[0][eb];       // (e0,e0,e1,e1)
            float4 A1 = *(const float4*)&ea_d[0][eb + 4];   // (e2,e2,e3,e3)
            float2 a00 = make_float2(A0.x, A0.y), a01 = make_float2(A0.z, A0.w);
            float2 a10 = make_float2(A1.x, A1.y), a11 = make_float2(A1.z, A1.w);
            t[0][0] = ffma2(a00, wv0, bv0);  t[0][1] = ffma2(a00, wv1, bv1);
            t[1][0] = ffma2(a01, wv0, bv0);  t[1][1] = ffma2(a01, wv1, bv1);
            t[2][0] = ffma2(a10, wv0, bv0);  t[2][1] = ffma2(a10, wv1, bv1);
            t[3][0] = ffma2(a11, wv0, bv0);  t[3][1] = ffma2(a11, wv1, bv1);
        }
#pragma unroll
        for (int j = 1; j < FBx; j++) {
            float4 Wv = *(const float4*)&W_s[buf][j][c];
            float2 wv0 = make_float2(Wv.x, Wv.y);
            float2 wv1 = make_float2(Wv.z, Wv.w);
            float4 A0 = *(const float4*)&ea_d[j][eb];
            float4 A1 = *(const float4*)&ea_d[j][eb + 4];
            float2 a00 = make_float2(A0.x, A0.y), a01 = make_float2(A0.z, A0.w);
            float2 a10 = make_float2(A1.x, A1.y), a11 = make_float2(A1.z, A1.w);
            t[0][0] = ffma2(a00, wv0, t[0][0]);  t[0][1] = ffma2(a00, wv1, t[0][1]);
            t[1][0] = ffma2(a01, wv0, t[1][0]);  t[1][1] = ffma2(a01, wv1, t[1][1]);
            t[2][0] = ffma2(a10, wv0, t[2][0]);  t[2][1] = ffma2(a10, wv1, t[2][1]);
            t[3][0] = ffma2(a11, wv0, t[3][0]);  t[3][1] = ffma2(a11, wv1, t[3][1]);
        }
        // acc += x_src[i] * relu(t)
        float4 X0 = *(const float4*)&xs_d[i][eb];
        float4 X1 = *(const float4*)&xs_d[i][eb + 4];
        float2 x00 = make_float2(X0.x, X0.y), x01 = make_float2(X0.z, X0.w);
        float2 x10 = make_float2(X1.x, X1.y), x11 = make_float2(X1.z, X1.w);
        acc[0][0] = ffma2(x00, relu2(t[0][0]), acc[0][0]);
        acc[0][1] = ffma2(x00, relu2(t[0][1]), acc[0][1]);
        acc[1][0] = ffma2(x01, relu2(t[1][0]), acc[1][0]);
        acc[1][1] = ffma2(x01, relu2(t[1][1]), acc[1][1]);
        acc[2][0] = ffma2(x10, relu2(t[2][0]), acc[2][0]);
        acc[2][1] = ffma2(x10, relu2(t[2][1]), acc[2][1]);
        acc[3][0] = ffma2(x11, relu2(t[3][0]), acc[3][0]);
        acc[3][1] = ffma2(x11, relu2(t[3][1]), acc[3][1]);

        __syncthreads();         // all warps done with buf before it is refilled
    }

    // scatter-add messages into destination nodes
    if (ok) {
#pragma unroll
        for (int e = 0; e < 4; e++) {
            int d = dst_s[4 * w + e];
            float* hr = &g_h[d * CCx + c];
            atomicAdd(hr + 0, acc[e][0].x);
            atomicAdd(hr + 1, acc[e][0].y);
            atomicAdd(hr + 2, acc[e][1].x);
            atomicAdd(hr + 3, acc[e][1].y);
        }
    }
}

// ---------------------------------------------------------------------------
// K3: per-channel sum & sumsq of relu(h). Read-only, float2, 4-way unrolled.
// ---------------------------------------------------------------------------
__global__ void __launch_bounds__(64)
k_stats() {
    const int c2 = threadIdx.x;            // blockDim = 64, active < 50
    if (c2 >= CCx / 2) return;
    const int cb = 2 * c2;
    float2 s = make_float2(0.f, 0.f);
    float2 q = make_float2(0.f, 0.f);
    const int stride = gridDim.x;
    int n = blockIdx.x;
    for (; n + 3 * stride < NN; n += 4 * stride) {
        float2 a = *(const float2*)&g_h[(n              ) * CCx + cb];
        float2 b = *(const float2*)&g_h[(n +     stride) * CCx + cb];
        float2 cc = *(const float2*)&g_h[(n + 2 * stride) * CCx + cb];
        float2 d = *(const float2*)&g_h[(n + 3 * stride) * CCx + cb];
        a = relu2(a); b = relu2(b); cc = relu2(cc); d = relu2(d);
        s.x += a.x + b.x + cc.x + d.x;  s.y += a.y + b.y + cc.y + d.y;
        q.x += a.x*a.x + b.x*b.x + cc.x*cc.x + d.x*d.x;
        q.y += a.y*a.y + b.y*b.y + cc.y*cc.y + d.y*d.y;
    }
    for (; n < NN; n += stride) {
        float2 a = relu2(*(const float2*)&g_h[n * CCx + cb]);
        s.x += a.x; s.y += a.y;
        q.x += a.x*a.x; q.y += a.y*a.y;
    }
    atomicAdd(&g_stats[cb],           s.x);
    atomicAdd(&g_stats[cb + 1],       s.y);
    atomicAdd(&g_stats[CCx + cb],     q.x);
    atomicAdd(&g_stats[CCx + cb + 1], q.y);
}

// ---------------------------------------------------------------------------
// K4: fused BN-apply + global_add_pool + output head, one block per molecule.
//   sum_n norm(relu(h)) = gamma*rstd*(S - cnt*mean) + cnt*beta
// ---------------------------------------------------------------------------
__device__ __forceinline__ int lower_bound_batch(const int* __restrict__ b, int key) {
    int lo = 0, hi = NN;
    while (lo < hi) {
        int mid = (lo + hi) >> 1;
        if (b[mid] < key) lo = mid + 1; else hi = mid;
    }
    return lo;
}

__global__ void __launch_bounds__(128)
k_pool_out(const float* __restrict__ gamma,
           const float* __restrict__ beta,
           const float* __restrict__ Wout,
           const float* __restrict__ bout,
           const int*   __restrict__ batch,
           float* __restrict__ out) {
    __shared__ int s_lo, s_hi;
    __shared__ float red[128];
    const int g = blockIdx.x;
    const int tid = threadIdx.x;
    if (tid == 0) s_lo = lower_bound_batch(batch, g);
    if (tid == 1) s_hi = lower_bound_batch(batch, g + 1);
    __syncthreads();
    const int lo = s_lo, hi = s_hi;

    float val = 0.f;
    if (tid < CCx) {
        float S = 0.f;
        for (int n = lo; n < hi; n++)
            S += fmaxf(g_h[n * CCx + tid], 0.f);
        float cnt  = (float)(hi - lo);
        float mean = g_stats[tid] * (1.f / NN);
        float var  = g_stats[CCx + tid] * (1.f / NN) - mean * mean;
        float rstd = rsqrtf(var + EPSV);
        float pooled = gamma[tid] * rstd * (S - cnt * mean) + cnt * beta[tid];
        val = fmaxf(pooled, 0.f) * Wout[tid];
    }
    red[tid] = val;
    __syncthreads();
#pragma unroll
    for (int o = 64; o; o >>= 1) {
        if (tid < o) red[tid] += red[tid + o];
        __syncthreads();
    }
    if (tid == 0) out[g] = red[0] + bout[0];
}

// ---------------------------------------------------------------------------
extern "C" void kernel_launch(void* const* d_in, const int* in_sizes, int n_in,
                              void* d_out, int out_size) {
    const float* x     = (const float*)d_in[0];   // [N, FA]
    const float* ea    = (const float*)d_in[1];   // [E, FB]
    const float* W1    = (const float*)d_in[2];   // [FB, FA*C]
    const float* b1    = (const float*)d_in[3];   // [FA*C]
    const float* Wr    = (const float*)d_in[4];   // [FA, C]
    const float* bias  = (const float*)d_in[5];   // [C]
    const float* gamma = (const float*)d_in[6];   // [C]
    const float* beta  = (const float*)d_in[7];   // [C]
    const float* Wout  = (const float*)d_in[8];   // [C, 1]
    const float* bout  = (const float*)d_in[9];   // [1]
    const int*   eidx  = (const int*)d_in[10];    // [2, E]
    const int*   batch = (const int*)d_in[11];    // [N]
    float* out = (float*)d_out;                   // [G, 1]

    k_zero<<<1, 256>>>();
    k_root<<<(NN + 7) / 8, 256>>>(x, Wr, bias);
    k_zero<<<1, 256>>>();   // cheap dup: shifts the profiler capture slot onto k_edge
    k_edge<<<EE / TBE, 128>>>(x, ea, W1, b1, eidx);
    k_stats<<<2500, 64>>>();
    k_pool_out<<<GGx, 128>>>(gamma, beta, Wout, bout, batch, out);
}

// round 16
// speedup vs baseline: 3.6735x; 1.1337x over previous
#include <cuda_runtime.h>
#include <cstdint>

// Problem dims (fixed per reference)
#define NN   20000
#define EE   40000
#define FAx  75
#define FBx  12
#define CCx  100
#define GGx  1000
#define EPSV 1e-5f

#define TBE 32   // edges per block (8 per warp)

// Scratch (static device arrays: no allocation allowed)
__device__ float g_h[NN * CCx];     // node features h [N, C] (pre-relu)
__device__ float g_stats[2 * CCx];  // [sum, sumsq] per channel of relu(h)

// ---------------------------------------------------------------------------
// packed f32x2 FMA (FFMA2) — only reachable via PTX
// ---------------------------------------------------------------------------
union F2U { float2 f2; unsigned long long u; };

__device__ __forceinline__ float2 ffma2(float2 a, float2 b, float2 c) {
    F2U ua, ub, uc, ud;
    ua.f2 = a; ub.f2 = b; uc.f2 = c;
    asm("fma.rn.f32x2 %0, %1, %2, %3;"
        : "=l"(ud.u) : "l"(ua.u), "l"(ub.u), "l"(uc.u));
    return ud.f2;
}
__device__ __forceinline__ float2 relu2(float2 v) {
    return make_float2(fmaxf(v.x, 0.f), fmaxf(v.y, 0.f));
}

// cp.async 16B helpers
__device__ __forceinline__ void cp_async16(void* sptr, const void* gptr) {
    unsigned int sa = (unsigned int)__cvta_generic_to_shared(sptr);
    asm volatile("cp.async.ca.shared.global [%0], [%1], 16;" :: "r"(sa), "l"(gptr));
}
#define CP_COMMIT()  asm volatile("cp.async.commit_group;")
#define CP_WAIT(n)   asm volatile("cp.async.wait_group %0;" :: "n"(n))

// ---------------------------------------------------------------------------
// K0: zero the batch-stat accumulator
// ---------------------------------------------------------------------------
__global__ void k_zero() {
    int t = threadIdx.x;
    if (t < 2 * CCx) g_stats[t] = 0.f;
}

// ---------------------------------------------------------------------------
// K1: h[n,c] = x[n,:] @ W_root[:,c] + bias[c]
// 256 threads = 8 warps = 8 nodes per block; lane<25 owns channel quad 4*lane.
// ---------------------------------------------------------------------------
__global__ void __launch_bounds__(256)
k_root(const float* __restrict__ x,
       const float* __restrict__ Wr,
       const float* __restrict__ bias) {
    __shared__ float xs[8][FAx + 1];
    const int tid = threadIdx.x;
    const int n0  = blockIdx.x * 8;

    for (int idx = tid; idx < 8 * FAx; idx += 256) {
        int e = idx / FAx, i = idx - e * FAx;
        int n = n0 + e;
        xs[e][i] = (n < NN) ? x[n * FAx + i] : 0.f;
    }
    __syncthreads();

    const int w = tid >> 5, lane = tid & 31;
    const int n = n0 + w;
    if (n >= NN || lane >= CCx / 4) return;
    const int c = 4 * lane;

    float4 B = *(const float4*)&bias[c];
    float2 a0 = make_float2(B.x, B.y);
    float2 a1 = make_float2(B.z, B.w);
#pragma unroll
    for (int i = 0; i < FAx; i++) {
        float xv = xs[w][i];
        float2 xp = make_float2(xv, xv);
        float4 Wv = *(const float4*)&Wr[i * CCx + c];
        a0 = ffma2(xp, make_float2(Wv.x, Wv.y), a0);
        a1 = ffma2(xp, make_float2(Wv.z, Wv.w), a1);
    }
    float4 o; o.x = a0.x; o.y = a0.y; o.z = a1.x; o.w = a1.y;
    *(float4*)&g_h[n * CCx + c] = o;
}

// ---------------------------------------------------------------------------
// K2: fused NNConv edge kernel, cp.async double-buffered W1 staging.
//   t[i,c] = b1[i*C+c] + sum_j ea[e,j]*W1[j, i*C+c]
//   msg[e,c] = sum_i x_src[e,i] * relu(t[i,c]); atomicAdd into g_h[dst[e],:]
// 128 thr = 4 warps; warp w owns edges [8w,8w+8); lane<25 owns channels
// 4*lane..4*lane+3 (two f32 pairs). ea / x staged duplicated (v,v).
// Per i, the 12x100 W1 slice + b1 slice live in smem (2 buffers), prefetched
// one i ahead. 8-edge register tile amortizes each distinct-lane W LDS over
// 16 FFMA2 (halves crossbar traffic per edge vs the 4-edge tile).
// ---------------------------------------------------------------------------
__global__ void __launch_bounds__(128, 3)
k_edge(const float* __restrict__ x,
       const float* __restrict__ ea,
       const float* __restrict__ W1,
       const float* __restrict__ b1,
       const int*   __restrict__ eidx) {
    __shared__ float W_s[2][FBx][CCx];     // 9.6 KB
    __shared__ float b_s[2][CCx];          // 0.8 KB
    __shared__ float ea_d[FBx][2 * TBE];   // duplicated pairs [12][64]
    __shared__ float xs_d[FAx][2 * TBE];   // duplicated pairs [75][64]
    __shared__ int   dst_s[TBE];

    const int tid = threadIdx.x;
    const int e0  = blockIdx.x * TBE;

    // ---- stage edge data ----
    for (int idx = tid; idx < TBE * FBx; idx += 128) {
        int e = idx / FBx, j = idx - e * FBx;
        float v = ea[(e0 + e) * FBx + j];
        ea_d[j][2 * e] = v; ea_d[j][2 * e + 1] = v;
    }
    if (tid < TBE) dst_s[tid] = eidx[EE + e0 + tid];
    for (int idx = tid; idx < TBE * FAx; idx += 128) {
        int e = idx / FAx, i = idx - e * FAx;
        int s = eidx[e0 + e];
        float v = x[s * FAx + i];
        xs_d[i][2 * e] = v; xs_d[i][2 * e + 1] = v;
    }

    // ---- prefetch W1/b1 slice for i = 0 ----
    // 300 float4 of W slice + 25 float4 of b1 slice = 325 cp.async per slice
    {
        for (int idx = tid; idx < 325; idx += 128) {
            if (idx < 300) {
                int j = idx / 25, q = idx - 25 * j;
                cp_async16(&W_s[0][j][4 * q], W1 + j * (FAx * CCx) + 4 * q);
            } else {
                int q = idx - 300;
                cp_async16(&b_s[0][4 * q], b1 + 4 * q);
            }
        }
        CP_COMMIT();
    }

    const int lane  = tid & 31;
    const int w     = tid >> 5;
    const bool ok   = (lane < CCx / 4);        // 25 active lanes
    const int  lc   = ok ? lane : (CCx / 4 - 1);
    const int  c    = 4 * lc;                  // channels c..c+3
    const int  eb   = 16 * w;                  // duplicated idx base (8 edges)

    float2 acc[8][2];
#pragma unroll
    for (int e = 0; e < 8; e++) {
        acc[e][0] = make_float2(0.f, 0.f);
        acc[e][1] = make_float2(0.f, 0.f);
    }

    for (int i = 0; i < FAx; i++) {
        const int buf = i & 1;
        // prefetch next slice into the other buffer
        if (i + 1 < FAx) {
            const float* Wsrc = W1 + (i + 1) * CCx;
            const float* bsrc = b1 + (i + 1) * CCx;
            float* Wdst = &W_s[buf ^ 1][0][0];
            float* bdst = &b_s[buf ^ 1][0];
            for (int idx = tid; idx < 325; idx += 128) {
                if (idx < 300) {
                    int j = idx / 25, q = idx - 25 * j;
                    cp_async16(Wdst + j * CCx + 4 * q, Wsrc + j * (FAx * CCx) + 4 * q);
                } else {
                    int q = idx - 300;
                    cp_async16(bdst + 4 * q, bsrc + 4 * q);
                }
            }
            CP_COMMIT();
            CP_WAIT(1);          // slice i complete (group before the one just committed)
        } else {
            CP_WAIT(0);
        }
        __syncthreads();         // slice i visible to all warps (also covers ea/xs on i=0)

        float4 B = *(const float4*)&b_s[buf][c];
        const float2 bv0 = make_float2(B.x, B.y);
        const float2 bv1 = make_float2(B.z, B.w);

        float2 t[8][2];
#pragma unroll
        for (int e = 0; e < 8; e++) { t[e][0] = bv0; t[e][1] = bv1; }

#pragma unroll
        for (int j = 0; j < FBx; j++) {
            float4 Wv = *(const float4*)&W_s[buf][j][c];
            float2 wv0 = make_float2(Wv.x, Wv.y);
            float2 wv1 = make_float2(Wv.z, Wv.w);
            float4 A0 = *(const float4*)&ea_d[j][eb];        // (e0,e0,e1,e1)
            float4 A1 = *(const float4*)&ea_d[j][eb + 4];    // (e2,e2,e3,e3)
            float4 A2 = *(const float4*)&ea_d[j][eb + 8];    // (e4,e4,e5,e5)
            float4 A3 = *(const float4*)&ea_d[j][eb + 12];   // (e6,e6,e7,e7)
            float2 a[8];
            a[0] = make_float2(A0.x, A0.y); a[1] = make_float2(A0.z, A0.w);
            a[2] = make_float2(A1.x, A1.y); a[3] = make_float2(A1.z, A1.w);
            a[4] = make_float2(A2.x, A2.y); a[5] = make_float2(A2.z, A2.w);
            a[6] = make_float2(A3.x, A3.y); a[7] = make_float2(A3.z, A3.w);
#pragma unroll
            for (int e = 0; e < 8; e++) {
                t[e][0] = ffma2(a[e], wv0, t[e][0]);
                t[e][1] = ffma2(a[e], wv1, t[e][1]);
            }
        }
        // acc += x_src[i] * relu(t)
        {
            float4 X0 = *(const float4*)&xs_d[i][eb];
            float4 X1 = *(const float4*)&xs_d[i][eb + 4];
            float4 X2 = *(const float4*)&xs_d[i][eb + 8];
            float4 X3 = *(const float4*)&xs_d[i][eb + 12];
            float2 xv[8];
            xv[0] = make_float2(X0.x, X0.y); xv[1] = make_float2(X0.z, X0.w);
            xv[2] = make_float2(X1.x, X1.y); xv[3] = make_float2(X1.z, X1.w);
            xv[4] = make_float2(X2.x, X2.y); xv[5] = make_float2(X2.z, X2.w);
            xv[6] = make_float2(X3.x, X3.y); xv[7] = make_float2(X3.z, X3.w);
#pragma unroll
            for (int e = 0; e < 8; e++) {
                acc[e][0] = ffma2(xv[e], relu2(t[e][0]), acc[e][0]);
                acc[e][1] = ffma2(xv[e], relu2(t[e][1]), acc[e][1]);
            }
        }

        __syncthreads();         // all warps done with buf before it is refilled
    }

    // scatter-add messages into destination nodes
    if (ok) {
#pragma unroll
        for (int e = 0; e < 8; e++) {
            int d = dst_s[8 * w + e];
            float* hr = &g_h[d * CCx + c];
            atomicAdd(hr + 0, acc[e][0].x);
            atomicAdd(hr + 1, acc[e][0].y);
            atomicAdd(hr + 2, acc[e][1].x);
            atomicAdd(hr + 3, acc[e][1].y);
        }
    }
}

// ---------------------------------------------------------------------------
// K3: per-channel sum & sumsq of relu(h). Read-only, float2, 4-way unrolled.
// ---------------------------------------------------------------------------
__global__ void __launch_bounds__(64)
k_stats() {
    const int c2 = threadIdx.x;            // blockDim = 64, active < 50
    if (c2 >= CCx / 2) return;
    const int cb = 2 * c2;
    float2 s = make_float2(0.f, 0.f);
    float2 q = make_float2(0.f, 0.f);
    const int stride = gridDim.x;
    int n = blockIdx.x;
    for (; n + 3 * stride < NN; n += 4 * stride) {
        float2 a = *(const float2*)&g_h[(n              ) * CCx + cb];
        float2 b = *(const float2*)&g_h[(n +     stride) * CCx + cb];
        float2 cc = *(const float2*)&g_h[(n + 2 * stride) * CCx + cb];
        float2 d = *(const float2*)&g_h[(n + 3 * stride) * CCx + cb];
        a = relu2(a); b = relu2(b); cc = relu2(cc); d = relu2(d);
        s.x += a.x + b.x + cc.x + d.x;  s.y += a.y + b.y + cc.y + d.y;
        q.x += a.x*a.x + b.x*b.x + cc.x*cc.x + d.x*d.x;
        q.y += a.y*a.y + b.y*b.y + cc.y*cc.y + d.y*d.y;
    }
    for (; n < NN; n += stride) {
        float2 a = relu2(*(const float2*)&g_h[n * CCx + cb]);
        s.x += a.x; s.y += a.y;
        q.x += a.x*a.x; q.y += a.y*a.y;
    }
    atomicAdd(&g_stats[cb],           s.x);
    atomicAdd(&g_stats[cb + 1],       s.y);
    atomicAdd(&g_stats[CCx + cb],     q.x);
    atomicAdd(&g_stats[CCx + cb + 1], q.y);
}

// ---------------------------------------------------------------------------
// K4: fused BN-apply + global_add_pool + output head, one block per molecule.
//   sum_n norm(relu(h)) = gamma*rstd*(S - cnt*mean) + cnt*beta
// ---------------------------------------------------------------------------
__device__ __forceinline__ int lower_bound_batch(const int* __restrict__ b, int key) {
    int lo = 0, hi = NN;
    while (lo < hi) {
        int mid = (lo + hi) >> 1;
        if (b[mid] < key) lo = mid + 1; else hi = mid;
    }
    return lo;
}

__global__ void __launch_bounds__(128)
k_pool_out(const float* __restrict__ gamma,
           const float* __restrict__ beta,
           const float* __restrict__ Wout,
           const float* __restrict__ bout,
           const int*   __restrict__ batch,
           float* __restrict__ out) {
    __shared__ int s_lo, s_hi;
    __shared__ float red[128];
    const int g = blockIdx.x;
    const int tid = threadIdx.x;
    if (tid == 0) s_lo = lower_bound_batch(batch, g);
    if (tid == 1) s_hi = lower_bound_batch(batch, g + 1);
    __syncthreads();
    const int lo = s_lo, hi = s_hi;

    float val = 0.f;
    if (tid < CCx) {
        float S = 0.f;
        for (int n = lo; n < hi; n++)
            S += fmaxf(g_h[n * CCx + tid], 0.f);
        float cnt  = (float)(hi - lo);
        float mean = g_stats[tid] * (1.f / NN);
        float var  = g_stats[CCx + tid] * (1.f / NN) - mean * mean;
        float rstd = rsqrtf(var + EPSV);
        float pooled = gamma[tid] * rstd * (S - cnt * mean) + cnt * beta[tid];
        val = fmaxf(pooled, 0.f) * Wout[tid];
    }
    red[tid] = val;
    __syncthreads();
#pragma unroll
    for (int o = 64; o; o >>= 1) {
        if (tid < o) red[tid] += red[tid + o];
        __syncthreads();
    }
    if (tid == 0) out[g] = red[0] + bout[0];
}

// ---------------------------------------------------------------------------
extern "C" void kernel_launch(void* const* d_in, const int* in_sizes, int n_in,
                              void* d_out, int out_size) {
    const float* x     = (const float*)d_in[0];   // [N, FA]
    const float* ea    = (const float*)d_in[1];   // [E, FB]
    const float* W1    = (const float*)d_in[2];   // [FB, FA*C]
    const float* b1    = (const float*)d_in[3];   // [FA*C]
    const float* Wr    = (const float*)d_in[4];   // [FA, C]
    const float* bias  = (const float*)d_in[5];   // [C]
    const float* gamma = (const float*)d_in[6];   // [C]
    const float* beta  = (const float*)d_in[7];   // [C]
    const float* Wout  = (const float*)d_in[8];   // [C, 1]
    const float* bout  = (const float*)d_in[9];   // [1]
    const int*   eidx  = (const int*)d_in[10];    // [2, E]
    const int*   batch = (const int*)d_in[11];    // [N]
    float* out = (float*)d_out;                   // [G, 1]

    k_zero<<<1, 256>>>();
    k_root<<<(NN + 7) / 8, 256>>>(x, Wr, bias);
    k_zero<<<1, 256>>>();   // cheap dup: keeps the profiler capture slot on k_edge
    k_edge<<<EE / TBE, 128>>>(x, ea, W1, b1, eidx);
    k_stats<<<2500, 64>>>();
    k_pool_out<<<GGx, 128>>>(gamma, beta, Wout, bout, batch, out);
}